// round 5
// baseline (speedup 1.0000x reference)
#include <cuda_runtime.h>
#include <cuda_bf16.h>
#include <stdint.h>
#include <math.h>

#define NS 50000
#define NA 50000
#define NEDGE 1600000

// Scratch (device globals; no allocation allowed)
__device__ __align__(16) float g_Apre[NA * 32];   // a2s src-side layer1 partial (+b1)
__device__ __align__(16) float g_Bpre[NS * 32];   // a2s dst-side layer1 partial
__device__ __align__(16) float g_Cpre[NS * 32];   // s2s src-side layer1 partial (+b1)
__device__ __align__(16) float g_Dpre[NS * 32];   // s2s dst-side layer1 partial
__device__ __align__(16) float g_sum_u[NS * 64];
__device__ __align__(16) float g_sum_h[NS * 64];

__device__ __forceinline__ float leaky(float x) { return fmaxf(x, 0.01f * x); }
__device__ __forceinline__ float tanh_fast(float x) {
    float r; asm("tanh.approx.f32 %0, %1;" : "=f"(r) : "f"(x)); return r;
}
__device__ __forceinline__ uint32_t smem_u32(const void* p) {
    uint32_t a;
    asm("{ .reg .u64 t; cvta.to.shared.u64 t, %1; cvt.u32.u64 %0, t; }"
        : "=r"(a) : "l"(p));
    return a;
}
__device__ __forceinline__ uint32_t pack_bf16x2(__nv_bfloat16 a, __nv_bfloat16 b) {
    // low 16 bits = a (smaller k), high = b
    uint16_t ua = *reinterpret_cast<uint16_t*>(&a);
    uint16_t ub = *reinterpret_cast<uint16_t*>(&b);
    return (uint32_t)ua | ((uint32_t)ub << 16);
}
__device__ __forceinline__ void ldsm_x4(uint32_t addr, uint32_t& a0, uint32_t& a1,
                                        uint32_t& a2, uint32_t& a3) {
    asm volatile("ldmatrix.sync.aligned.m8n8.x4.shared.b16 {%0,%1,%2,%3}, [%4];"
                 : "=r"(a0), "=r"(a1), "=r"(a2), "=r"(a3) : "r"(addr));
}
__device__ __forceinline__ void mma_bf16(float& c0, float& c1, float& c2, float& c3,
                                         uint32_t a0, uint32_t a1, uint32_t a2, uint32_t a3,
                                         uint32_t b0, uint32_t b1) {
    asm volatile(
        "mma.sync.aligned.m16n8k16.row.col.f32.bf16.bf16.f32 "
        "{%0,%1,%2,%3}, {%4,%5,%6,%7}, {%8,%9}, {%0,%1,%2,%3};"
        : "+f"(c0), "+f"(c1), "+f"(c2), "+f"(c3)
        : "r"(a0), "r"(a1), "r"(a2), "r"(a3), "r"(b0), "r"(b1));
}

// ---------------------------------------------------------------------------
// Fused node-side precompute (unchanged)
// ---------------------------------------------------------------------------
__global__ void __launch_bounds__(256) pre_kernel(
    const float* __restrict__ pos_s,
    const float* __restrict__ pos_a,
    const float* __restrict__ u,
    const float* __restrict__ h,
    const float* __restrict__ a2s_W1, const float* __restrict__ a2s_b1,
    const float* __restrict__ s2s_W1, const float* __restrict__ s2s_b1)
{
    int lane = threadIdx.x & 31;
    int task = (blockIdx.x * blockDim.x + threadIdx.x) >> 5;

    if (task < NS) {
        int node = task;
        float p0 = __ldg(pos_s + 2 * node);
        float p1 = __ldg(pos_s + 2 * node + 1);
        g_Bpre[node * 32 + lane] =
            p0 * __ldg(a2s_W1 + 2 * 32 + lane) + p1 * __ldg(a2s_W1 + 3 * 32 + lane);
        g_Dpre[node * 32 + lane] =
            p0 * __ldg(s2s_W1 + 2 * 32 + lane) + p1 * __ldg(s2s_W1 + 3 * 32 + lane);
        g_sum_u[node * 64 + lane]      = 0.f;
        g_sum_u[node * 64 + 32 + lane] = 0.f;
        g_sum_h[node * 64 + lane]      = 0.f;
        g_sum_h[node * 64 + 32 + lane] = 0.f;
    } else if (task < NS + NA) {
        int node = task - NS;
        const float* W1 = a2s_W1;
        float p0 = __ldg(pos_a + 2 * node);
        float p1 = __ldg(pos_a + 2 * node + 1);
        float acc = __ldg(a2s_b1 + lane)
                  + p0 * __ldg(W1 + 0 * 32 + lane)
                  + p1 * __ldg(W1 + 1 * 32 + lane);
        const float4* u4 = reinterpret_cast<const float4*>(u) + node * 4;
#pragma unroll
        for (int q = 0; q < 4; ++q) {
            float4 v = __ldg(u4 + q);
            acc = fmaf(v.x, __ldg(W1 + (5 + 4 * q + 0) * 32 + lane), acc);
            acc = fmaf(v.y, __ldg(W1 + (5 + 4 * q + 1) * 32 + lane), acc);
            acc = fmaf(v.z, __ldg(W1 + (5 + 4 * q + 2) * 32 + lane), acc);
            acc = fmaf(v.w, __ldg(W1 + (5 + 4 * q + 3) * 32 + lane), acc);
        }
        g_Apre[node * 32 + lane] = acc;
    } else if (task < NS + NA + NS) {
        int node = task - NS - NA;
        const float* W1 = s2s_W1;
        float p0 = __ldg(pos_s + 2 * node);
        float p1 = __ldg(pos_s + 2 * node + 1);
        float acc = __ldg(s2s_b1 + lane)
                  + p0 * __ldg(W1 + 0 * 32 + lane)
                  + p1 * __ldg(W1 + 1 * 32 + lane);
        const float4* h4 = reinterpret_cast<const float4*>(h) + node * 16;
#pragma unroll
        for (int q = 0; q < 16; ++q) {
            float4 v = __ldg(h4 + q);
            acc = fmaf(v.x, __ldg(W1 + (5 + 4 * q + 0) * 32 + lane), acc);
            acc = fmaf(v.y, __ldg(W1 + (5 + 4 * q + 1) * 32 + lane), acc);
            acc = fmaf(v.z, __ldg(W1 + (5 + 4 * q + 2) * 32 + lane), acc);
            acc = fmaf(v.w, __ldg(W1 + (5 + 4 * q + 3) * 32 + lane), acc);
        }
        g_Cpre[node * 32 + lane] = acc;
    }
}

// ---------------------------------------------------------------------------
// Edge kernel with mma.sync (bf16, 3-term split).
// CTA = 128 threads = 4 warps; each warp owns 64 edges (2 subtiles of 32).
// Per subtile:
//   stage: hid = leaky(Asrc[s] + Bdst[d] + dis*w1d); split hi/lo bf16,
//          store into smem A tile: row = edge (0..31), row stride 144B,
//          bytes [0,64) = hi[32], [64,128) = lo[32]  (conflict-free ldmatrix)
//   A frags via ldmatrix.x4; W2 hi/lo frags in registers (loaded once);
//   C init = bias; 3 terms x 32 HMMA; tanh.approx; red.v2 scatter.
// Blocks [0,EB) = a2s, [EB,2EB) = s2s.  NEDGE % 256 == 0.
// ---------------------------------------------------------------------------
#define ROWB 144   // A-tile row stride in bytes

__global__ void __launch_bounds__(128) edge_mma_kernel(
    int eb,
    const int* __restrict__ src0, const int* __restrict__ dst0,
    const float* __restrict__ dis0,
    const float* __restrict__ W10, const float* __restrict__ W20,
    const float* __restrict__ b20,
    const int* __restrict__ src1, const int* __restrict__ dst1,
    const float* __restrict__ dis1,
    const float* __restrict__ W11, const float* __restrict__ W21,
    const float* __restrict__ b21)
{
    __shared__ __align__(16) char sA[4][32 * ROWB];

    int tid  = threadIdx.x;
    int wid  = tid >> 5;
    int lane = tid & 31;

    bool second = (blockIdx.x >= (unsigned)eb);
    int blk = second ? ((int)blockIdx.x - eb) : (int)blockIdx.x;

    const int*   src = second ? src1 : src0;
    const int*   dst = second ? dst1 : dst0;
    const float* dis = second ? dis1 : dis0;
    const float* W1  = second ? W11  : W10;
    const float* W2  = second ? W21  : W20;
    const float* b2  = second ? b21  : b20;
    const float* __restrict__ Asrc = second ? g_Cpre : g_Apre;
    const float* __restrict__ Bdst = second ? g_Dpre : g_Bpre;
    float* __restrict__ sumbuf     = second ? g_sum_h : g_sum_u;

    char* warp_tile = sA[wid];
    uint32_t tile_base = smem_u32(warp_tile);

    float w1d = __ldg(W1 + 4 * 32 + lane);

    // ---- W2 fragments (hi/lo), loaded once per warp ----
    // B frag (k16 x n8) for tile (nt, kt): n = nt*8 + lane>>2, k0 = kt*16 + 2*(lane&3)
    // b0 = (W2[k0][n], W2[k0+1][n]), b1 = (W2[k0+8][n], W2[k0+9][n])
    uint32_t Bhi[8][2][2], Blo[8][2][2];
    {
        int n = (lane >> 2);
#pragma unroll
        for (int nt = 0; nt < 8; ++nt) {
#pragma unroll
            for (int kt = 0; kt < 2; ++kt) {
                int k0 = kt * 16 + 2 * (lane & 3);
                float w00 = __ldg(W2 + (k0 + 0) * 64 + nt * 8 + n);
                float w01 = __ldg(W2 + (k0 + 1) * 64 + nt * 8 + n);
                float w10 = __ldg(W2 + (k0 + 8) * 64 + nt * 8 + n);
                float w11 = __ldg(W2 + (k0 + 9) * 64 + nt * 8 + n);
                __nv_bfloat16 h00 = __float2bfloat16(w00);
                __nv_bfloat16 h01 = __float2bfloat16(w01);
                __nv_bfloat16 h10 = __float2bfloat16(w10);
                __nv_bfloat16 h11 = __float2bfloat16(w11);
                Bhi[nt][kt][0] = pack_bf16x2(h00, h01);
                Bhi[nt][kt][1] = pack_bf16x2(h10, h11);
                Blo[nt][kt][0] = pack_bf16x2(
                    __float2bfloat16(w00 - __bfloat162float(h00)),
                    __float2bfloat16(w01 - __bfloat162float(h01)));
                Blo[nt][kt][1] = pack_bf16x2(
                    __float2bfloat16(w10 - __bfloat162float(h10)),
                    __float2bfloat16(w11 - __bfloat162float(h11)));
            }
        }
    }
    // Bias for C fragments: cols n = nt*8 + 2*(lane&3) + {0,1}
    float biasA[8], biasB[8];
#pragma unroll
    for (int nt = 0; nt < 8; ++nt) {
        biasA[nt] = __ldg(b2 + nt * 8 + 2 * (lane & 3));
        biasB[nt] = __ldg(b2 + nt * 8 + 2 * (lane & 3) + 1);
    }

    int gwarp = blk * 4 + wid;

#pragma unroll 1
    for (int sub = 0; sub < 2; ++sub) {
        int ebase = gwarp * 64 + sub * 32;
        int s    = __ldg(src + ebase + lane);
        int d    = __ldg(dst + ebase + lane);
        float dv = __ldg(dis + ebase + lane);

        // ---- stage hid tile ----
#pragma unroll 4
        for (int t = 0; t < 32; ++t) {
            int ss   = __shfl_sync(0xffffffffu, s, t);
            int dd   = __shfl_sync(0xffffffffu, d, t);
            float dw = __shfl_sync(0xffffffffu, dv, t);
            float hid = __ldg(Asrc + ss * 32 + lane)
                      + __ldg(Bdst + dd * 32 + lane)
                      + dw * w1d;
            hid = leaky(hid);
            __nv_bfloat16 hi = __float2bfloat16(hid);
            __nv_bfloat16 lo = __float2bfloat16(hid - __bfloat162float(hi));
            *reinterpret_cast<__nv_bfloat16*>(warp_tile + t * ROWB + lane * 2) = hi;
            *reinterpret_cast<__nv_bfloat16*>(warp_tile + t * ROWB + 64 + lane * 2) = lo;
        }
        __syncwarp();

        // ---- C init with bias ----
        float C[2][8][4];
#pragma unroll
        for (int mt = 0; mt < 2; ++mt)
#pragma unroll
            for (int nt = 0; nt < 8; ++nt) {
                C[mt][nt][0] = biasA[nt];
                C[mt][nt][1] = biasB[nt];
                C[mt][nt][2] = biasA[nt];
                C[mt][nt][3] = biasB[nt];
            }

        // ldmatrix lane address pieces
        uint32_t lrow   = ((lane >> 3) & 1) * 8 + (lane & 7);
        uint32_t lchunk = (lane >> 4) * 16;

#pragma unroll
        for (int mt = 0; mt < 2; ++mt) {
            uint32_t rbase = tile_base + (mt * 16 + lrow) * ROWB + lchunk;
            uint32_t ah[2][4], al[2][4];
            ldsm_x4(rbase + 0,  ah[0][0], ah[0][1], ah[0][2], ah[0][3]);   // hi kt0
            ldsm_x4(rbase + 32, ah[1][0], ah[1][1], ah[1][2], ah[1][3]);   // hi kt1
            ldsm_x4(rbase + 64, al[0][0], al[0][1], al[0][2], al[0][3]);   // lo kt0
            ldsm_x4(rbase + 96, al[1][0], al[1][1], al[1][2], al[1][3]);   // lo kt1
#pragma unroll
            for (int nt = 0; nt < 8; ++nt) {
#pragma unroll
                for (int kt = 0; kt < 2; ++kt) {
                    // Ahi*Whi + Ahi*Wlo + Alo*Whi
                    mma_bf16(C[mt][nt][0], C[mt][nt][1], C[mt][nt][2], C[mt][nt][3],
                             ah[kt][0], ah[kt][1], ah[kt][2], ah[kt][3],
                             Bhi[nt][kt][0], Bhi[nt][kt][1]);
                    mma_bf16(C[mt][nt][0], C[mt][nt][1], C[mt][nt][2], C[mt][nt][3],
                             ah[kt][0], ah[kt][1], ah[kt][2], ah[kt][3],
                             Blo[nt][kt][0], Blo[nt][kt][1]);
                    mma_bf16(C[mt][nt][0], C[mt][nt][1], C[mt][nt][2], C[mt][nt][3],
                             al[kt][0], al[kt][1], al[kt][2], al[kt][3],
                             Bhi[nt][kt][0], Bhi[nt][kt][1]);
                }
            }
        }
        __syncwarp();

        // ---- epilogue: tanh + scatter ----
#pragma unroll
        for (int mt = 0; mt < 2; ++mt) {
            int dd0 = __shfl_sync(0xffffffffu, d, mt * 16 + (lane >> 2));
            int dd1 = __shfl_sync(0xffffffffu, d, mt * 16 + 8 + (lane >> 2));
            float* r0 = sumbuf + (size_t)dd0 * 64 + 2 * (lane & 3);
            float* r1 = sumbuf + (size_t)dd1 * 64 + 2 * (lane & 3);
#pragma unroll
            for (int nt = 0; nt < 8; ++nt) {
                float t0 = tanh_fast(C[mt][nt][0]);
                float t1 = tanh_fast(C[mt][nt][1]);
                float t2 = tanh_fast(C[mt][nt][2]);
                float t3 = tanh_fast(C[mt][nt][3]);
                asm volatile("red.global.add.v2.f32 [%0], {%1, %2};"
                             :: "l"(r0 + nt * 8), "f"(t0), "f"(t1) : "memory");
                asm volatile("red.global.add.v2.f32 [%0], {%1, %2};"
                             :: "l"(r1 + nt * 8), "f"(t2), "f"(t3) : "memory");
            }
        }
    }
}

// ---------------------------------------------------------------------------
// Node update (unchanged): [pos_s, h, sum_u, sum_h] -> 32 -> 64, tanh.
// ---------------------------------------------------------------------------
__global__ void __launch_bounds__(256) upd_kernel(
    const float* __restrict__ pos_s,
    const float* __restrict__ h,
    const float* __restrict__ W1,
    const float* __restrict__ b1,
    const float* __restrict__ W2,
    const float* __restrict__ b2,
    float* __restrict__ out)
{
    int lane = threadIdx.x & 31;
    int node = (blockIdx.x * blockDim.x + threadIdx.x) >> 5;
    if (node >= NS) return;
    float p0 = __ldg(pos_s + 2 * node);
    float p1 = __ldg(pos_s + 2 * node + 1);
    float acc = __ldg(b1 + lane)
              + p0 * __ldg(W1 + 0 * 32 + lane)
              + p1 * __ldg(W1 + 1 * 32 + lane);

    const float4* h4  = reinterpret_cast<const float4*>(h) + node * 16;
    const float4* su4 = reinterpret_cast<const float4*>(g_sum_u) + node * 16;
    const float4* sh4 = reinterpret_cast<const float4*>(g_sum_h) + node * 16;
#pragma unroll
    for (int q = 0; q < 16; ++q) {
        float4 v = __ldg(h4 + q);
        acc = fmaf(v.x, __ldg(W1 + (2 + 4 * q + 0) * 32 + lane), acc);
        acc = fmaf(v.y, __ldg(W1 + (2 + 4 * q + 1) * 32 + lane), acc);
        acc = fmaf(v.z, __ldg(W1 + (2 + 4 * q + 2) * 32 + lane), acc);
        acc = fmaf(v.w, __ldg(W1 + (2 + 4 * q + 3) * 32 + lane), acc);
    }
#pragma unroll
    for (int q = 0; q < 16; ++q) {
        float4 v = su4[q];
        acc = fmaf(v.x, __ldg(W1 + (66 + 4 * q + 0) * 32 + lane), acc);
        acc = fmaf(v.y, __ldg(W1 + (66 + 4 * q + 1) * 32 + lane), acc);
        acc = fmaf(v.z, __ldg(W1 + (66 + 4 * q + 2) * 32 + lane), acc);
        acc = fmaf(v.w, __ldg(W1 + (66 + 4 * q + 3) * 32 + lane), acc);
    }
#pragma unroll
    for (int q = 0; q < 16; ++q) {
        float4 v = sh4[q];
        acc = fmaf(v.x, __ldg(W1 + (130 + 4 * q + 0) * 32 + lane), acc);
        acc = fmaf(v.y, __ldg(W1 + (130 + 4 * q + 1) * 32 + lane), acc);
        acc = fmaf(v.z, __ldg(W1 + (130 + 4 * q + 2) * 32 + lane), acc);
        acc = fmaf(v.w, __ldg(W1 + (130 + 4 * q + 3) * 32 + lane), acc);
    }
    acc = leaky(acc);

    float m0 = __ldg(b2 + 2 * lane);
    float m1 = __ldg(b2 + 2 * lane + 1);
#pragma unroll
    for (int k = 0; k < 32; ++k) {
        float hv = __shfl_sync(0xffffffffu, acc, k);
        float2 wv = __ldg(reinterpret_cast<const float2*>(W2 + k * 64) + lane);
        m0 = fmaf(hv, wv.x, m0);
        m1 = fmaf(hv, wv.y, m1);
    }
    float2 o;
    o.x = tanhf(m0);
    o.y = tanhf(m1);
    reinterpret_cast<float2*>(out)[node * 32 + lane] = o;
}

// ---------------------------------------------------------------------------
extern "C" void kernel_launch(void* const* d_in, const int* in_sizes, int n_in,
                              void* d_out, int out_size)
{
    const float* h        = (const float*)d_in[0];
    const float* u        = (const float*)d_in[1];
    const float* pos_s    = (const float*)d_in[2];
    const float* pos_a    = (const float*)d_in[3];
    const float* dis_a2s  = (const float*)d_in[4];
    const float* dis_s2s  = (const float*)d_in[5];
    const int*   a2s_src  = (const int*)d_in[6];
    const int*   a2s_dst  = (const int*)d_in[7];
    const int*   s2s_src  = (const int*)d_in[8];
    const int*   s2s_dst  = (const int*)d_in[9];
    const float* a2s_W1   = (const float*)d_in[10];
    const float* a2s_b1   = (const float*)d_in[11];
    const float* a2s_W2   = (const float*)d_in[12];
    const float* a2s_b2   = (const float*)d_in[13];
    const float* s2s_W1   = (const float*)d_in[14];
    const float* s2s_b1   = (const float*)d_in[15];
    const float* s2s_W2   = (const float*)d_in[16];
    const float* s2s_b2   = (const float*)d_in[17];
    const float* upd_W1   = (const float*)d_in[18];
    const float* upd_b1   = (const float*)d_in[19];
    const float* upd_W2   = (const float*)d_in[20];
    const float* upd_b2   = (const float*)d_in[21];
    float* out = (float*)d_out;

    const int WPB = 8;

    // Fused node-side precompute
    int pre_tasks = NS + NA + NS;
    pre_kernel<<<(pre_tasks + WPB - 1) / WPB, 256>>>(
        pos_s, pos_a, u, h, a2s_W1, a2s_b1, s2s_W1, s2s_b1);

    // Edge passes on tensor cores (mma.sync): 256 edges per CTA
    int eb = NEDGE / 256;                 // 6250 per pass
    edge_mma_kernel<<<2 * eb, 128>>>(
        eb,
        a2s_src, a2s_dst, dis_a2s, a2s_W1, a2s_W2, a2s_b2,
        s2s_src, s2s_dst, dis_s2s, s2s_W1, s2s_W2, s2s_b2);

    // Node update
    upd_kernel<<<(NS + WPB - 1) / WPB, 256>>>(pos_s, h, upd_W1, upd_b1, upd_W2, upd_b2, out);
}

// round 6
// speedup vs baseline: 1.3053x; 1.3053x over previous
#include <cuda_runtime.h>
#include <cuda_bf16.h>
#include <stdint.h>
#include <math.h>

#define NS 50000
#define NA 50000
#define NEDGE 1600000

// Scratch (device globals; no allocation allowed)
__device__ __align__(16) float g_Apre[NA * 32];   // a2s src-side layer1 partial (+b1)
__device__ __align__(16) float g_Bpre[NS * 32];   // a2s dst-side layer1 partial
__device__ __align__(16) float g_Cpre[NS * 32];   // s2s src-side layer1 partial (+b1)
__device__ __align__(16) float g_Dpre[NS * 32];   // s2s dst-side layer1 partial
__device__ __align__(16) float g_sum_u[NS * 64];
__device__ __align__(16) float g_sum_h[NS * 64];

__device__ __forceinline__ float leaky(float x) { return fmaxf(x, 0.01f * x); }
__device__ __forceinline__ float tanh_fast(float x) {
    float r; asm("tanh.approx.f32 %0, %1;" : "=f"(r) : "f"(x)); return r;
}
__device__ __forceinline__ uint32_t smem_u32(const void* p) {
    uint32_t a;
    asm("{ .reg .u64 t; cvta.to.shared.u64 t, %1; cvt.u32.u64 %0, t; }"
        : "=r"(a) : "l"(p));
    return a;
}
__device__ __forceinline__ uint32_t pack_bf16x2(__nv_bfloat16 a, __nv_bfloat16 b) {
    uint16_t ua = *reinterpret_cast<uint16_t*>(&a);
    uint16_t ub = *reinterpret_cast<uint16_t*>(&b);
    return (uint32_t)ua | ((uint32_t)ub << 16);
}
__device__ __forceinline__ void ldsm_x4(uint32_t addr, uint32_t& a0, uint32_t& a1,
                                        uint32_t& a2, uint32_t& a3) {
    asm volatile("ldmatrix.sync.aligned.m8n8.x4.shared.b16 {%0,%1,%2,%3}, [%4];"
                 : "=r"(a0), "=r"(a1), "=r"(a2), "=r"(a3) : "r"(addr));
}
__device__ __forceinline__ void mma_bf16(float& c0, float& c1, float& c2, float& c3,
                                         uint32_t a0, uint32_t a1, uint32_t a2, uint32_t a3,
                                         uint32_t b0, uint32_t b1) {
    asm volatile(
        "mma.sync.aligned.m16n8k16.row.col.f32.bf16.bf16.f32 "
        "{%0,%1,%2,%3}, {%4,%5,%6,%7}, {%8,%9}, {%0,%1,%2,%3};"
        : "+f"(c0), "+f"(c1), "+f"(c2), "+f"(c3)
        : "r"(a0), "r"(a1), "r"(a2), "r"(a3), "r"(b0), "r"(b1));
}

// ---------------------------------------------------------------------------
// Fused node-side precompute (unchanged)
// ---------------------------------------------------------------------------
__global__ void __launch_bounds__(256) pre_kernel(
    const float* __restrict__ pos_s,
    const float* __restrict__ pos_a,
    const float* __restrict__ u,
    const float* __restrict__ h,
    const float* __restrict__ a2s_W1, const float* __restrict__ a2s_b1,
    const float* __restrict__ s2s_W1, const float* __restrict__ s2s_b1)
{
    int lane = threadIdx.x & 31;
    int task = (blockIdx.x * blockDim.x + threadIdx.x) >> 5;

    if (task < NS) {
        int node = task;
        float p0 = __ldg(pos_s + 2 * node);
        float p1 = __ldg(pos_s + 2 * node + 1);
        g_Bpre[node * 32 + lane] =
            p0 * __ldg(a2s_W1 + 2 * 32 + lane) + p1 * __ldg(a2s_W1 + 3 * 32 + lane);
        g_Dpre[node * 32 + lane] =
            p0 * __ldg(s2s_W1 + 2 * 32 + lane) + p1 * __ldg(s2s_W1 + 3 * 32 + lane);
        g_sum_u[node * 64 + lane]      = 0.f;
        g_sum_u[node * 64 + 32 + lane] = 0.f;
        g_sum_h[node * 64 + lane]      = 0.f;
        g_sum_h[node * 64 + 32 + lane] = 0.f;
    } else if (task < NS + NA) {
        int node = task - NS;
        const float* W1 = a2s_W1;
        float p0 = __ldg(pos_a + 2 * node);
        float p1 = __ldg(pos_a + 2 * node + 1);
        float acc = __ldg(a2s_b1 + lane)
                  + p0 * __ldg(W1 + 0 * 32 + lane)
                  + p1 * __ldg(W1 + 1 * 32 + lane);
        const float4* u4 = reinterpret_cast<const float4*>(u) + node * 4;
#pragma unroll
        for (int q = 0; q < 4; ++q) {
            float4 v = __ldg(u4 + q);
            acc = fmaf(v.x, __ldg(W1 + (5 + 4 * q + 0) * 32 + lane), acc);
            acc = fmaf(v.y, __ldg(W1 + (5 + 4 * q + 1) * 32 + lane), acc);
            acc = fmaf(v.z, __ldg(W1 + (5 + 4 * q + 2) * 32 + lane), acc);
            acc = fmaf(v.w, __ldg(W1 + (5 + 4 * q + 3) * 32 + lane), acc);
        }
        g_Apre[node * 32 + lane] = acc;
    } else if (task < NS + NA + NS) {
        int node = task - NS - NA;
        const float* W1 = s2s_W1;
        float p0 = __ldg(pos_s + 2 * node);
        float p1 = __ldg(pos_s + 2 * node + 1);
        float acc = __ldg(s2s_b1 + lane)
                  + p0 * __ldg(W1 + 0 * 32 + lane)
                  + p1 * __ldg(W1 + 1 * 32 + lane);
        const float4* h4 = reinterpret_cast<const float4*>(h) + node * 16;
#pragma unroll
        for (int q = 0; q < 16; ++q) {
            float4 v = __ldg(h4 + q);
            acc = fmaf(v.x, __ldg(W1 + (5 + 4 * q + 0) * 32 + lane), acc);
            acc = fmaf(v.y, __ldg(W1 + (5 + 4 * q + 1) * 32 + lane), acc);
            acc = fmaf(v.z, __ldg(W1 + (5 + 4 * q + 2) * 32 + lane), acc);
            acc = fmaf(v.w, __ldg(W1 + (5 + 4 * q + 3) * 32 + lane), acc);
        }
        g_Cpre[node * 32 + lane] = acc;
    }
}

// ---------------------------------------------------------------------------
// Edge kernel, mma.sync bf16 3-term split, occupancy-oriented layout.
// CTA = 128 thr / 4 warps, handles 256 edges (warp: 2 tiles of 32 edges).
// B-fragments (hi/lo) pre-packed once per CTA into an 8KB smem table, loaded
// per N-half with 8x LDS.128 (32 regs live). C processed per (half, mt):
// 16 floats live. A frags 16 live. Fragment index math identical to R5
// (verified correct, rel_err 6e-6).
// Blocks [0,EB) = a2s, [EB,2EB) = s2s.  NEDGE % 256 == 0.
// ---------------------------------------------------------------------------
#define ROWB 144   // A-tile row stride in bytes

__global__ void __launch_bounds__(128, 4) edge_mma_kernel(
    int eb,
    const int* __restrict__ src0, const int* __restrict__ dst0,
    const float* __restrict__ dis0,
    const float* __restrict__ W10, const float* __restrict__ W20,
    const float* __restrict__ b20,
    const int* __restrict__ src1, const int* __restrict__ dst1,
    const float* __restrict__ dis1,
    const float* __restrict__ W11, const float* __restrict__ W21,
    const float* __restrict__ b21)
{
    __shared__ __align__(16) char sA[4][32 * ROWB];          // 18432 B
    __shared__ __align__(16) uint32_t sBF[2][8][32][4];      // 8192 B

    int tid  = threadIdx.x;
    int wid  = tid >> 5;
    int lane = tid & 31;

    bool second = (blockIdx.x >= (unsigned)eb);
    int blk = second ? ((int)blockIdx.x - eb) : (int)blockIdx.x;

    const int*   src = second ? src1 : src0;
    const int*   dst = second ? dst1 : dst0;
    const float* dis = second ? dis1 : dis0;
    const float* W1  = second ? W11  : W10;
    const float* W2  = second ? W21  : W20;
    const float* b2  = second ? b21  : b20;
    const float* __restrict__ Asrc = second ? g_Cpre : g_Apre;
    const float* __restrict__ Bdst = second ? g_Dpre : g_Bpre;
    float* __restrict__ sumbuf     = second ? g_sum_h : g_sum_u;

    // ---- build B-fragment table (once per CTA) ----
    // word w: 0 = hi pair0, 1 = hi pair1, 2 = lo pair0, 3 = lo pair1
    // group g: nt_l = g>>1, kt = g&1 (nt_l local to half)
#pragma unroll
    for (int f = tid; f < 2048; f += 128) {
        int w      = f & 3;
        int lane_i = (f >> 2) & 31;
        int g      = (f >> 7) & 7;
        int half   = f >> 10;
        int nt_l   = g >> 1;
        int kt     = g & 1;
        int n  = (half * 4 + nt_l) * 8 + (lane_i >> 2);
        int k0 = kt * 16 + 2 * (lane_i & 3) + (w & 1) * 8;
        float w0 = __ldg(W2 + (k0 + 0) * 64 + n);
        float w1 = __ldg(W2 + (k0 + 1) * 64 + n);
        __nv_bfloat16 h0 = __float2bfloat16(w0);
        __nv_bfloat16 h1 = __float2bfloat16(w1);
        uint32_t val;
        if ((w >> 1) == 0) {
            val = pack_bf16x2(h0, h1);
        } else {
            val = pack_bf16x2(__float2bfloat16(w0 - __bfloat162float(h0)),
                              __float2bfloat16(w1 - __bfloat162float(h1)));
        }
        sBF[half][g][lane_i][w] = val;
    }
    __syncthreads();

    char* warp_tile = sA[wid];
    uint32_t tile_base = smem_u32(warp_tile);

    float w1d = __ldg(W1 + 4 * 32 + lane);

    // Bias per fragment columns: col = (half*4+nt_l)*8 + 2*(lane&3) + {0,1}
    float biasA[2][4], biasB[2][4];
#pragma unroll
    for (int half = 0; half < 2; ++half)
#pragma unroll
        for (int nt = 0; nt < 4; ++nt) {
            biasA[half][nt] = __ldg(b2 + (half * 4 + nt) * 8 + 2 * (lane & 3));
            biasB[half][nt] = __ldg(b2 + (half * 4 + nt) * 8 + 2 * (lane & 3) + 1);
        }

    // ldmatrix lane address pieces (identical to R5)
    uint32_t lrow   = ((lane >> 3) & 1) * 8 + (lane & 7);
    uint32_t lchunk = (lane >> 4) * 16;

    int gwarp = blk * 4 + wid;

#pragma unroll 1
    for (int tile = 0; tile < 2; ++tile) {
        int ebase = gwarp * 64 + tile * 32;
        int s    = __ldg(src + ebase + lane);
        int d    = __ldg(dst + ebase + lane);
        float dv = __ldg(dis + ebase + lane);

        // ---- stage hid tile (hi/lo bf16) ----
#pragma unroll 4
        for (int t = 0; t < 32; ++t) {
            int ss   = __shfl_sync(0xffffffffu, s, t);
            int dd   = __shfl_sync(0xffffffffu, d, t);
            float dw = __shfl_sync(0xffffffffu, dv, t);
            float hid = __ldg(Asrc + ss * 32 + lane)
                      + __ldg(Bdst + dd * 32 + lane)
                      + dw * w1d;
            hid = leaky(hid);
            __nv_bfloat16 hi = __float2bfloat16(hid);
            __nv_bfloat16 lo = __float2bfloat16(hid - __bfloat162float(hi));
            *reinterpret_cast<__nv_bfloat16*>(warp_tile + t * ROWB + lane * 2) = hi;
            *reinterpret_cast<__nv_bfloat16*>(warp_tile + t * ROWB + 64 + lane * 2) = lo;
        }
        __syncwarp();

#pragma unroll
        for (int half = 0; half < 2; ++half) {
            // ---- load B fragments for this half: 8x LDS.128 ----
            uint32_t Bh[4][2][2], Bl[4][2][2];
#pragma unroll
            for (int g = 0; g < 8; ++g) {
                uint4 v = *reinterpret_cast<const uint4*>(&sBF[half][g][lane][0]);
                int nt = g >> 1, kt = g & 1;
                Bh[nt][kt][0] = v.x;
                Bh[nt][kt][1] = v.y;
                Bl[nt][kt][0] = v.z;
                Bl[nt][kt][1] = v.w;
            }

#pragma unroll
            for (int mt = 0; mt < 2; ++mt) {
                uint32_t rbase = tile_base + (mt * 16 + lrow) * ROWB + lchunk;
                uint32_t ah[2][4], al[2][4];
                ldsm_x4(rbase + 0,  ah[0][0], ah[0][1], ah[0][2], ah[0][3]);
                ldsm_x4(rbase + 32, ah[1][0], ah[1][1], ah[1][2], ah[1][3]);
                ldsm_x4(rbase + 64, al[0][0], al[0][1], al[0][2], al[0][3]);
                ldsm_x4(rbase + 96, al[1][0], al[1][1], al[1][2], al[1][3]);

                float C[4][4];
#pragma unroll
                for (int nt = 0; nt < 4; ++nt) {
                    C[nt][0] = biasA[half][nt];
                    C[nt][1] = biasB[half][nt];
                    C[nt][2] = biasA[half][nt];
                    C[nt][3] = biasB[half][nt];
                }

#pragma unroll
                for (int nt = 0; nt < 4; ++nt) {
#pragma unroll
                    for (int kt = 0; kt < 2; ++kt) {
                        mma_bf16(C[nt][0], C[nt][1], C[nt][2], C[nt][3],
                                 ah[kt][0], ah[kt][1], ah[kt][2], ah[kt][3],
                                 Bh[nt][kt][0], Bh[nt][kt][1]);
                        mma_bf16(C[nt][0], C[nt][1], C[nt][2], C[nt][3],
                                 ah[kt][0], ah[kt][1], ah[kt][2], ah[kt][3],
                                 Bl[nt][kt][0], Bl[nt][kt][1]);
                        mma_bf16(C[nt][0], C[nt][1], C[nt][2], C[nt][3],
                                 al[kt][0], al[kt][1], al[kt][2], al[kt][3],
                                 Bh[nt][kt][0], Bh[nt][kt][1]);
                    }
                }

                // ---- epilogue for (half, mt): tanh + scatter ----
                int dd0 = __shfl_sync(0xffffffffu, d, mt * 16 + (lane >> 2));
                int dd1 = __shfl_sync(0xffffffffu, d, mt * 16 + 8 + (lane >> 2));
                float* r0 = sumbuf + (size_t)dd0 * 64 + half * 32 + 2 * (lane & 3);
                float* r1 = sumbuf + (size_t)dd1 * 64 + half * 32 + 2 * (lane & 3);
#pragma unroll
                for (int nt = 0; nt < 4; ++nt) {
                    float t0 = tanh_fast(C[nt][0]);
                    float t1 = tanh_fast(C[nt][1]);
                    float t2 = tanh_fast(C[nt][2]);
                    float t3 = tanh_fast(C[nt][3]);
                    asm volatile("red.global.add.v2.f32 [%0], {%1, %2};"
                                 :: "l"(r0 + nt * 8), "f"(t0), "f"(t1) : "memory");
                    asm volatile("red.global.add.v2.f32 [%0], {%1, %2};"
                                 :: "l"(r1 + nt * 8), "f"(t2), "f"(t3) : "memory");
                }
            }
        }
        __syncwarp();
    }
}

// ---------------------------------------------------------------------------
// Node update (unchanged): [pos_s, h, sum_u, sum_h] -> 32 -> 64, tanh.
// ---------------------------------------------------------------------------
__global__ void __launch_bounds__(256) upd_kernel(
    const float* __restrict__ pos_s,
    const float* __restrict__ h,
    const float* __restrict__ W1,
    const float* __restrict__ b1,
    const float* __restrict__ W2,
    const float* __restrict__ b2,
    float* __restrict__ out)
{
    int lane = threadIdx.x & 31;
    int node = (blockIdx.x * blockDim.x + threadIdx.x) >> 5;
    if (node >= NS) return;
    float p0 = __ldg(pos_s + 2 * node);
    float p1 = __ldg(pos_s + 2 * node + 1);
    float acc = __ldg(b1 + lane)
              + p0 * __ldg(W1 + 0 * 32 + lane)
              + p1 * __ldg(W1 + 1 * 32 + lane);

    const float4* h4  = reinterpret_cast<const float4*>(h) + node * 16;
    const float4* su4 = reinterpret_cast<const float4*>(g_sum_u) + node * 16;
    const float4* sh4 = reinterpret_cast<const float4*>(g_sum_h) + node * 16;
#pragma unroll
    for (int q = 0; q < 16; ++q) {
        float4 v = __ldg(h4 + q);
        acc = fmaf(v.x, __ldg(W1 + (2 + 4 * q + 0) * 32 + lane), acc);
        acc = fmaf(v.y, __ldg(W1 + (2 + 4 * q + 1) * 32 + lane), acc);
        acc = fmaf(v.z, __ldg(W1 + (2 + 4 * q + 2) * 32 + lane), acc);
        acc = fmaf(v.w, __ldg(W1 + (2 + 4 * q + 3) * 32 + lane), acc);
    }
#pragma unroll
    for (int q = 0; q < 16; ++q) {
        float4 v = su4[q];
        acc = fmaf(v.x, __ldg(W1 + (66 + 4 * q + 0) * 32 + lane), acc);
        acc = fmaf(v.y, __ldg(W1 + (66 + 4 * q + 1) * 32 + lane), acc);
        acc = fmaf(v.z, __ldg(W1 + (66 + 4 * q + 2) * 32 + lane), acc);
        acc = fmaf(v.w, __ldg(W1 + (66 + 4 * q + 3) * 32 + lane), acc);
    }
#pragma unroll
    for (int q = 0; q < 16; ++q) {
        float4 v = sh4[q];
        acc = fmaf(v.x, __ldg(W1 + (130 + 4 * q + 0) * 32 + lane), acc);
        acc = fmaf(v.y, __ldg(W1 + (130 + 4 * q + 1) * 32 + lane), acc);
        acc = fmaf(v.z, __ldg(W1 + (130 + 4 * q + 2) * 32 + lane), acc);
        acc = fmaf(v.w, __ldg(W1 + (130 + 4 * q + 3) * 32 + lane), acc);
    }
    acc = leaky(acc);

    float m0 = __ldg(b2 + 2 * lane);
    float m1 = __ldg(b2 + 2 * lane + 1);
#pragma unroll
    for (int k = 0; k < 32; ++k) {
        float hv = __shfl_sync(0xffffffffu, acc, k);
        float2 wv = __ldg(reinterpret_cast<const float2*>(W2 + k * 64) + lane);
        m0 = fmaf(hv, wv.x, m0);
        m1 = fmaf(hv, wv.y, m1);
    }
    float2 o;
    o.x = tanhf(m0);
    o.y = tanhf(m1);
    reinterpret_cast<float2*>(out)[node * 32 + lane] = o;
}

// ---------------------------------------------------------------------------
extern "C" void kernel_launch(void* const* d_in, const int* in_sizes, int n_in,
                              void* d_out, int out_size)
{
    const float* h        = (const float*)d_in[0];
    const float* u        = (const float*)d_in[1];
    const float* pos_s    = (const float*)d_in[2];
    const float* pos_a    = (const float*)d_in[3];
    const float* dis_a2s  = (const float*)d_in[4];
    const float* dis_s2s  = (const float*)d_in[5];
    const int*   a2s_src  = (const int*)d_in[6];
    const int*   a2s_dst  = (const int*)d_in[7];
    const int*   s2s_src  = (const int*)d_in[8];
    const int*   s2s_dst  = (const int*)d_in[9];
    const float* a2s_W1   = (const float*)d_in[10];
    const float* a2s_b1   = (const float*)d_in[11];
    const float* a2s_W2   = (const float*)d_in[12];
    const float* a2s_b2   = (const float*)d_in[13];
    const float* s2s_W1   = (const float*)d_in[14];
    const float* s2s_b1   = (const float*)d_in[15];
    const float* s2s_W2   = (const float*)d_in[16];
    const float* s2s_b2   = (const float*)d_in[17];
    const float* upd_W1   = (const float*)d_in[18];
    const float* upd_b1   = (const float*)d_in[19];
    const float* upd_W2   = (const float*)d_in[20];
    const float* upd_b2   = (const float*)d_in[21];
    float* out = (float*)d_out;

    const int WPB = 8;

    // Fused node-side precompute
    int pre_tasks = NS + NA + NS;
    pre_kernel<<<(pre_tasks + WPB - 1) / WPB, 256>>>(
        pos_s, pos_a, u, h, a2s_W1, a2s_b1, s2s_W1, s2s_b1);

    // Edge passes on tensor cores (mma.sync): 256 edges per CTA
    int eb = NEDGE / 256;                 // 6250 per pass
    edge_mma_kernel<<<2 * eb, 128>>>(
        eb,
        a2s_src, a2s_dst, dis_a2s, a2s_W1, a2s_W2, a2s_b2,
        s2s_src, s2s_dst, dis_s2s, s2s_W1, s2s_W2, s2s_b2);

    // Node update
    upd_kernel<<<(NS + WPB - 1) / WPB, 256>>>(pos_s, h, upd_W1, upd_b1, upd_W2, upd_b2, out);
}

// round 7
// speedup vs baseline: 1.3098x; 1.0034x over previous
#include <cuda_runtime.h>
#include <cuda_bf16.h>
#include <stdint.h>
#include <math.h>

#define NS 50000
#define NA 50000
#define NEDGE 1600000

// Scratch (device globals; no allocation allowed)
__device__ __align__(16) float g_Apre[NA * 32];   // a2s src-side layer1 partial (+b1)
__device__ __align__(16) float g_Bpre[NS * 32];   // a2s dst-side layer1 partial
__device__ __align__(16) float g_Cpre[NS * 32];   // s2s src-side layer1 partial (+b1)
__device__ __align__(16) float g_Dpre[NS * 32];   // s2s dst-side layer1 partial
__device__ __align__(16) float g_sum_u[NS * 64];
__device__ __align__(16) float g_sum_h[NS * 64];

__device__ __forceinline__ float leaky(float x) { return fmaxf(x, 0.01f * x); }
__device__ __forceinline__ float tanh_fast(float x) {
    float r; asm("tanh.approx.f32 %0, %1;" : "=f"(r) : "f"(x)); return r;
}
__device__ __forceinline__ uint32_t smem_u32(const void* p) {
    uint32_t a;
    asm("{ .reg .u64 t; cvta.to.shared.u64 t, %1; cvt.u32.u64 %0, t; }"
        : "=r"(a) : "l"(p));
    return a;
}
__device__ __forceinline__ uint32_t pack_bf16x2(__nv_bfloat16 a, __nv_bfloat16 b) {
    uint16_t ua = *reinterpret_cast<uint16_t*>(&a);
    uint16_t ub = *reinterpret_cast<uint16_t*>(&b);
    return (uint32_t)ua | ((uint32_t)ub << 16);
}
// pack (lo_elem, hi_elem) -> bf16x2 with lo_elem in low 16 bits
__device__ __forceinline__ uint32_t cvt_bf16x2(float lo_elem, float hi_elem) {
    uint32_t r;
    asm("cvt.rn.bf16x2.f32 %0, %1, %2;" : "=r"(r) : "f"(hi_elem), "f"(lo_elem));
    return r;
}
__device__ __forceinline__ void ldsm_x4(uint32_t addr, uint32_t& a0, uint32_t& a1,
                                        uint32_t& a2, uint32_t& a3) {
    asm volatile("ldmatrix.sync.aligned.m8n8.x4.shared.b16 {%0,%1,%2,%3}, [%4];"
                 : "=r"(a0), "=r"(a1), "=r"(a2), "=r"(a3) : "r"(addr));
}
__device__ __forceinline__ void mma_bf16(float& c0, float& c1, float& c2, float& c3,
                                         uint32_t a0, uint32_t a1, uint32_t a2, uint32_t a3,
                                         uint32_t b0, uint32_t b1) {
    asm volatile(
        "mma.sync.aligned.m16n8k16.row.col.f32.bf16.bf16.f32 "
        "{%0,%1,%2,%3}, {%4,%5,%6,%7}, {%8,%9}, {%0,%1,%2,%3};"
        : "+f"(c0), "+f"(c1), "+f"(c2), "+f"(c3)
        : "r"(a0), "r"(a1), "r"(a2), "r"(a3), "r"(b0), "r"(b1));
}

// ---------------------------------------------------------------------------
// Fused node-side precompute (unchanged)
// ---------------------------------------------------------------------------
__global__ void __launch_bounds__(256) pre_kernel(
    const float* __restrict__ pos_s,
    const float* __restrict__ pos_a,
    const float* __restrict__ u,
    const float* __restrict__ h,
    const float* __restrict__ a2s_W1, const float* __restrict__ a2s_b1,
    const float* __restrict__ s2s_W1, const float* __restrict__ s2s_b1)
{
    int lane = threadIdx.x & 31;
    int task = (blockIdx.x * blockDim.x + threadIdx.x) >> 5;

    if (task < NS) {
        int node = task;
        float p0 = __ldg(pos_s + 2 * node);
        float p1 = __ldg(pos_s + 2 * node + 1);
        g_Bpre[node * 32 + lane] =
            p0 * __ldg(a2s_W1 + 2 * 32 + lane) + p1 * __ldg(a2s_W1 + 3 * 32 + lane);
        g_Dpre[node * 32 + lane] =
            p0 * __ldg(s2s_W1 + 2 * 32 + lane) + p1 * __ldg(s2s_W1 + 3 * 32 + lane);
        g_sum_u[node * 64 + lane]      = 0.f;
        g_sum_u[node * 64 + 32 + lane] = 0.f;
        g_sum_h[node * 64 + lane]      = 0.f;
        g_sum_h[node * 64 + 32 + lane] = 0.f;
    } else if (task < NS + NA) {
        int node = task - NS;
        const float* W1 = a2s_W1;
        float p0 = __ldg(pos_a + 2 * node);
        float p1 = __ldg(pos_a + 2 * node + 1);
        float acc = __ldg(a2s_b1 + lane)
                  + p0 * __ldg(W1 + 0 * 32 + lane)
                  + p1 * __ldg(W1 + 1 * 32 + lane);
        const float4* u4 = reinterpret_cast<const float4*>(u) + node * 4;
#pragma unroll
        for (int q = 0; q < 4; ++q) {
            float4 v = __ldg(u4 + q);
            acc = fmaf(v.x, __ldg(W1 + (5 + 4 * q + 0) * 32 + lane), acc);
            acc = fmaf(v.y, __ldg(W1 + (5 + 4 * q + 1) * 32 + lane), acc);
            acc = fmaf(v.z, __ldg(W1 + (5 + 4 * q + 2) * 32 + lane), acc);
            acc = fmaf(v.w, __ldg(W1 + (5 + 4 * q + 3) * 32 + lane), acc);
        }
        g_Apre[node * 32 + lane] = acc;
    } else if (task < NS + NA + NS) {
        int node = task - NS - NA;
        const float* W1 = s2s_W1;
        float p0 = __ldg(pos_s + 2 * node);
        float p1 = __ldg(pos_s + 2 * node + 1);
        float acc = __ldg(s2s_b1 + lane)
                  + p0 * __ldg(W1 + 0 * 32 + lane)
                  + p1 * __ldg(W1 + 1 * 32 + lane);
        const float4* h4 = reinterpret_cast<const float4*>(h) + node * 16;
#pragma unroll
        for (int q = 0; q < 16; ++q) {
            float4 v = __ldg(h4 + q);
            acc = fmaf(v.x, __ldg(W1 + (5 + 4 * q + 0) * 32 + lane), acc);
            acc = fmaf(v.y, __ldg(W1 + (5 + 4 * q + 1) * 32 + lane), acc);
            acc = fmaf(v.z, __ldg(W1 + (5 + 4 * q + 2) * 32 + lane), acc);
            acc = fmaf(v.w, __ldg(W1 + (5 + 4 * q + 3) * 32 + lane), acc);
        }
        g_Cpre[node * 32 + lane] = acc;
    }
}

// ---------------------------------------------------------------------------
// Edge kernel, mma.sync bf16 3-term split (fragment math identical to R5/R6,
// verified rel_err 6e-6). R7 changes:
//  - staging: 4 edges/iter, 8 lanes/edge, LDG.128 gathers, cvt.rn.bf16x2
//    packing, STS.64 stores; row stride 192B for conflict-free stores
//  - C init from smem bias copy (LDS.64) instead of register bias tables
//  - __launch_bounds__(128, 5): 20 warps/SM
// Blocks [0,EB) = a2s, [EB,2EB) = s2s.  NEDGE % 256 == 0.
// ---------------------------------------------------------------------------
#define ROWB 192   // A-tile row stride in bytes (hi at +0..63, lo at +64..127)

__global__ void __launch_bounds__(128, 5) edge_mma_kernel(
    int eb,
    const int* __restrict__ src0, const int* __restrict__ dst0,
    const float* __restrict__ dis0,
    const float* __restrict__ W10, const float* __restrict__ W20,
    const float* __restrict__ b20,
    const int* __restrict__ src1, const int* __restrict__ dst1,
    const float* __restrict__ dis1,
    const float* __restrict__ W11, const float* __restrict__ W21,
    const float* __restrict__ b21)
{
    __shared__ __align__(16) char sA[4][32 * ROWB];          // 24576 B
    __shared__ __align__(16) uint32_t sBF[2][8][32][4];      // 8192 B
    __shared__ __align__(16) float sb2[64];                  // 256 B

    int tid  = threadIdx.x;
    int wid  = tid >> 5;
    int lane = tid & 31;

    bool second = (blockIdx.x >= (unsigned)eb);
    int blk = second ? ((int)blockIdx.x - eb) : (int)blockIdx.x;

    const int*   src = second ? src1 : src0;
    const int*   dst = second ? dst1 : dst0;
    const float* dis = second ? dis1 : dis0;
    const float* W1  = second ? W11  : W10;
    const float* W2  = second ? W21  : W20;
    const float* b2  = second ? b21  : b20;
    const float* __restrict__ Asrc = second ? g_Cpre : g_Apre;
    const float* __restrict__ Bdst = second ? g_Dpre : g_Bpre;
    float* __restrict__ sumbuf     = second ? g_sum_h : g_sum_u;

    // ---- bias copy + B-fragment table (once per CTA) ----
    if (tid < 64) sb2[tid] = __ldg(b2 + tid);
#pragma unroll
    for (int f = tid; f < 2048; f += 128) {
        int w      = f & 3;
        int lane_i = (f >> 2) & 31;
        int g      = (f >> 7) & 7;
        int half   = f >> 10;
        int nt_l   = g >> 1;
        int kt     = g & 1;
        int n  = (half * 4 + nt_l) * 8 + (lane_i >> 2);
        int k0 = kt * 16 + 2 * (lane_i & 3) + (w & 1) * 8;
        float w0 = __ldg(W2 + (k0 + 0) * 64 + n);
        float w1 = __ldg(W2 + (k0 + 1) * 64 + n);
        __nv_bfloat16 h0 = __float2bfloat16(w0);
        __nv_bfloat16 h1 = __float2bfloat16(w1);
        uint32_t val;
        if ((w >> 1) == 0) {
            val = pack_bf16x2(h0, h1);
        } else {
            val = pack_bf16x2(__float2bfloat16(w0 - __bfloat162float(h0)),
                              __float2bfloat16(w1 - __bfloat162float(h1)));
        }
        sBF[half][g][lane_i][w] = val;
    }
    __syncthreads();

    char* warp_tile = sA[wid];
    uint32_t tile_base = smem_u32(warp_tile);

    // per-lane staging constants: this lane covers elements (lane&7)*4 + {0..3}
    int eslot = lane >> 3;               // which of 4 edges per iteration
    int echunk = lane & 7;               // 16B chunk within the 32-float row
    float4 w1d4 = __ldg(reinterpret_cast<const float4*>(W1 + 4 * 32) + echunk);

    // ldmatrix lane address pieces (identical mapping to R5/R6)
    uint32_t lrow   = ((lane >> 3) & 1) * 8 + (lane & 7);
    uint32_t lchunk = (lane >> 4) * 16;

    int gwarp = blk * 4 + wid;

#pragma unroll 1
    for (int tile = 0; tile < 2; ++tile) {
        int ebase = gwarp * 64 + tile * 32;
        int s    = __ldg(src + ebase + lane);
        int d    = __ldg(dst + ebase + lane);
        float dv = __ldg(dis + ebase + lane);

        // ---- stage hid tile: 8 iterations x 4 edges ----
#pragma unroll 2
        for (int t = 0; t < 8; ++t) {
            int e = t * 4 + eslot;
            int ss   = __shfl_sync(0xffffffffu, s, e);
            int dd   = __shfl_sync(0xffffffffu, d, e);
            float dw = __shfl_sync(0xffffffffu, dv, e);
            float4 av = __ldg(reinterpret_cast<const float4*>(Asrc + ss * 32) + echunk);
            float4 bv = __ldg(reinterpret_cast<const float4*>(Bdst + dd * 32) + echunk);
            float h0 = leaky(av.x + bv.x + dw * w1d4.x);
            float h1 = leaky(av.y + bv.y + dw * w1d4.y);
            float h2 = leaky(av.z + bv.z + dw * w1d4.z);
            float h3 = leaky(av.w + bv.w + dw * w1d4.w);
            uint32_t hi01 = cvt_bf16x2(h0, h1);
            uint32_t hi23 = cvt_bf16x2(h2, h3);
            // lo = h - f32(bf16(h)); bf16->f32 via bit shifts of the packed pair
            float l0 = h0 - __uint_as_float(hi01 << 16);
            float l1 = h1 - __uint_as_float(hi01 & 0xffff0000u);
            float l2 = h2 - __uint_as_float(hi23 << 16);
            float l3 = h3 - __uint_as_float(hi23 & 0xffff0000u);
            uint32_t lo01 = cvt_bf16x2(l0, l1);
            uint32_t lo23 = cvt_bf16x2(l2, l3);
            char* rowp = warp_tile + e * ROWB + echunk * 8;
            *reinterpret_cast<uint2*>(rowp)      = make_uint2(hi01, hi23);
            *reinterpret_cast<uint2*>(rowp + 64) = make_uint2(lo01, lo23);
        }
        __syncwarp();

#pragma unroll
        for (int half = 0; half < 2; ++half) {
            // ---- load B fragments for this half: 8x LDS.128 ----
            uint32_t Bh[4][2][2], Bl[4][2][2];
#pragma unroll
            for (int g = 0; g < 8; ++g) {
                uint4 v = *reinterpret_cast<const uint4*>(&sBF[half][g][lane][0]);
                int nt = g >> 1, kt = g & 1;
                Bh[nt][kt][0] = v.x;
                Bh[nt][kt][1] = v.y;
                Bl[nt][kt][0] = v.z;
                Bl[nt][kt][1] = v.w;
            }

#pragma unroll
            for (int mt = 0; mt < 2; ++mt) {
                uint32_t rbase = tile_base + (mt * 16 + lrow) * ROWB + lchunk;
                uint32_t ah[2][4], al[2][4];
                ldsm_x4(rbase + 0,  ah[0][0], ah[0][1], ah[0][2], ah[0][3]);
                ldsm_x4(rbase + 32, ah[1][0], ah[1][1], ah[1][2], ah[1][3]);
                ldsm_x4(rbase + 64, al[0][0], al[0][1], al[0][2], al[0][3]);
                ldsm_x4(rbase + 96, al[1][0], al[1][1], al[1][2], al[1][3]);

                float C[4][4];
#pragma unroll
                for (int nt = 0; nt < 4; ++nt) {
                    float2 bb = *reinterpret_cast<const float2*>(
                        &sb2[(half * 4 + nt) * 8 + 2 * (lane & 3)]);
                    C[nt][0] = bb.x;
                    C[nt][1] = bb.y;
                    C[nt][2] = bb.x;
                    C[nt][3] = bb.y;
                }

#pragma unroll
                for (int nt = 0; nt < 4; ++nt) {
#pragma unroll
                    for (int kt = 0; kt < 2; ++kt) {
                        mma_bf16(C[nt][0], C[nt][1], C[nt][2], C[nt][3],
                                 ah[kt][0], ah[kt][1], ah[kt][2], ah[kt][3],
                                 Bh[nt][kt][0], Bh[nt][kt][1]);
                        mma_bf16(C[nt][0], C[nt][1], C[nt][2], C[nt][3],
                                 ah[kt][0], ah[kt][1], ah[kt][2], ah[kt][3],
                                 Bl[nt][kt][0], Bl[nt][kt][1]);
                        mma_bf16(C[nt][0], C[nt][1], C[nt][2], C[nt][3],
                                 al[kt][0], al[kt][1], al[kt][2], al[kt][3],
                                 Bh[nt][kt][0], Bh[nt][kt][1]);
                    }
                }

                // ---- epilogue for (half, mt): tanh + scatter ----
                int dd0 = __shfl_sync(0xffffffffu, d, mt * 16 + (lane >> 2));
                int dd1 = __shfl_sync(0xffffffffu, d, mt * 16 + 8 + (lane >> 2));
                float* r0 = sumbuf + (size_t)dd0 * 64 + half * 32 + 2 * (lane & 3);
                float* r1 = sumbuf + (size_t)dd1 * 64 + half * 32 + 2 * (lane & 3);
#pragma unroll
                for (int nt = 0; nt < 4; ++nt) {
                    float t0 = tanh_fast(C[nt][0]);
                    float t1 = tanh_fast(C[nt][1]);
                    float t2 = tanh_fast(C[nt][2]);
                    float t3 = tanh_fast(C[nt][3]);
                    asm volatile("red.global.add.v2.f32 [%0], {%1, %2};"
                                 :: "l"(r0 + nt * 8), "f"(t0), "f"(t1) : "memory");
                    asm volatile("red.global.add.v2.f32 [%0], {%1, %2};"
                                 :: "l"(r1 + nt * 8), "f"(t2), "f"(t3) : "memory");
                }
            }
        }
        __syncwarp();
    }
}

// ---------------------------------------------------------------------------
// Node update (unchanged): [pos_s, h, sum_u, sum_h] -> 32 -> 64, tanh.
// ---------------------------------------------------------------------------
__global__ void __launch_bounds__(256) upd_kernel(
    const float* __restrict__ pos_s,
    const float* __restrict__ h,
    const float* __restrict__ W1,
    const float* __restrict__ b1,
    const float* __restrict__ W2,
    const float* __restrict__ b2,
    float* __restrict__ out)
{
    int lane = threadIdx.x & 31;
    int node = (blockIdx.x * blockDim.x + threadIdx.x) >> 5;
    if (node >= NS) return;
    float p0 = __ldg(pos_s + 2 * node);
    float p1 = __ldg(pos_s + 2 * node + 1);
    float acc = __ldg(b1 + lane)
              + p0 * __ldg(W1 + 0 * 32 + lane)
              + p1 * __ldg(W1 + 1 * 32 + lane);

    const float4* h4  = reinterpret_cast<const float4*>(h) + node * 16;
    const float4* su4 = reinterpret_cast<const float4*>(g_sum_u) + node * 16;
    const float4* sh4 = reinterpret_cast<const float4*>(g_sum_h) + node * 16;
#pragma unroll
    for (int q = 0; q < 16; ++q) {
        float4 v = __ldg(h4 + q);
        acc = fmaf(v.x, __ldg(W1 + (2 + 4 * q + 0) * 32 + lane), acc);
        acc = fmaf(v.y, __ldg(W1 + (2 + 4 * q + 1) * 32 + lane), acc);
        acc = fmaf(v.z, __ldg(W1 + (2 + 4 * q + 2) * 32 + lane), acc);
        acc = fmaf(v.w, __ldg(W1 + (2 + 4 * q + 3) * 32 + lane), acc);
    }
#pragma unroll
    for (int q = 0; q < 16; ++q) {
        float4 v = su4[q];
        acc = fmaf(v.x, __ldg(W1 + (66 + 4 * q + 0) * 32 + lane), acc);
        acc = fmaf(v.y, __ldg(W1 + (66 + 4 * q + 1) * 32 + lane), acc);
        acc = fmaf(v.z, __ldg(W1 + (66 + 4 * q + 2) * 32 + lane), acc);
        acc = fmaf(v.w, __ldg(W1 + (66 + 4 * q + 3) * 32 + lane), acc);
    }
#pragma unroll
    for (int q = 0; q < 16; ++q) {
        float4 v = sh4[q];
        acc = fmaf(v.x, __ldg(W1 + (130 + 4 * q + 0) * 32 + lane), acc);
        acc = fmaf(v.y, __ldg(W1 + (130 + 4 * q + 1) * 32 + lane), acc);
        acc = fmaf(v.z, __ldg(W1 + (130 + 4 * q + 2) * 32 + lane), acc);
        acc = fmaf(v.w, __ldg(W1 + (130 + 4 * q + 3) * 32 + lane), acc);
    }
    acc = leaky(acc);

    float m0 = __ldg(b2 + 2 * lane);
    float m1 = __ldg(b2 + 2 * lane + 1);
#pragma unroll
    for (int k = 0; k < 32; ++k) {
        float hv = __shfl_sync(0xffffffffu, acc, k);
        float2 wv = __ldg(reinterpret_cast<const float2*>(W2 + k * 64) + lane);
        m0 = fmaf(hv, wv.x, m0);
        m1 = fmaf(hv, wv.y, m1);
    }
    float2 o;
    o.x = tanhf(m0);
    o.y = tanhf(m1);
    reinterpret_cast<float2*>(out)[node * 32 + lane] = o;
}

// ---------------------------------------------------------------------------
extern "C" void kernel_launch(void* const* d_in, const int* in_sizes, int n_in,
                              void* d_out, int out_size)
{
    const float* h        = (const float*)d_in[0];
    const float* u        = (const float*)d_in[1];
    const float* pos_s    = (const float*)d_in[2];
    const float* pos_a    = (const float*)d_in[3];
    const float* dis_a2s  = (const float*)d_in[4];
    const float* dis_s2s  = (const float*)d_in[5];
    const int*   a2s_src  = (const int*)d_in[6];
    const int*   a2s_dst  = (const int*)d_in[7];
    const int*   s2s_src  = (const int*)d_in[8];
    const int*   s2s_dst  = (const int*)d_in[9];
    const float* a2s_W1   = (const float*)d_in[10];
    const float* a2s_b1   = (const float*)d_in[11];
    const float* a2s_W2   = (const float*)d_in[12];
    const float* a2s_b2   = (const float*)d_in[13];
    const float* s2s_W1   = (const float*)d_in[14];
    const float* s2s_b1   = (const float*)d_in[15];
    const float* s2s_W2   = (const float*)d_in[16];
    const float* s2s_b2   = (const float*)d_in[17];
    const float* upd_W1   = (const float*)d_in[18];
    const float* upd_b1   = (const float*)d_in[19];
    const float* upd_W2   = (const float*)d_in[20];
    const float* upd_b2   = (const float*)d_in[21];
    float* out = (float*)d_out;

    const int WPB = 8;

    // Fused node-side precompute
    int pre_tasks = NS + NA + NS;
    pre_kernel<<<(pre_tasks + WPB - 1) / WPB, 256>>>(
        pos_s, pos_a, u, h, a2s_W1, a2s_b1, s2s_W1, s2s_b1);

    // Edge passes on tensor cores (mma.sync): 256 edges per CTA
    int eb = NEDGE / 256;                 // 6250 per pass
    edge_mma_kernel<<<2 * eb, 128>>>(
        eb,
        a2s_src, a2s_dst, dis_a2s, a2s_W1, a2s_W2, a2s_b2,
        s2s_src, s2s_dst, dis_s2s, s2s_W1, s2s_W2, s2s_b2);

    // Node update
    upd_kernel<<<(NS + WPB - 1) / WPB, 256>>>(pos_s, h, upd_W1, upd_b1, upd_W2, upd_b2, out);
}